// round 2
// baseline (speedup 1.0000x reference)
#include <cuda_runtime.h>
#include <cstdint>

// ---------------------------------------------------------------------------
// AdjGCN: 3-layer GCN forward.
//   layer: h = X @ W ; msgs = h[src]*w ; agg = segment_sum(msgs, dst) ; +b ; relu
//   final: log_softmax
// Scratch: two __device__ global buffers (N x 128 each), ping-ponged.
// Edge index dtype (int32 vs int64) is detected on-device at runtime.
// ---------------------------------------------------------------------------

#define MAXN 100000
#define DH   128
#define DO   40

__device__ float g_bufA[(size_t)MAXN * DH];
__device__ float g_bufB[(size_t)MAXN * DH];
__device__ int   g_idx64;   // 1 if edge_index is int64, 0 if int32

// ---------------------------------------------------------------------------
// Probe edge_index dtype. If the data is really int64 with values in [0, N),
// every 8-byte word is < N. If it's int32 data misread as int64, the high
// 32 bits hold the next index (almost surely nonzero somewhere in 32 probes).
// ---------------------------------------------------------------------------
__global__ void detect_idx_kernel(const void* ei, int n_nodes) {
    const long long* p = (const long long*)ei;
    int ok64 = 1;
    for (int i = 0; i < 32; i++) {
        long long v = p[i];
        if (v < 0 || v >= n_nodes) { ok64 = 0; break; }
    }
    g_idx64 = ok64;
}

__device__ __forceinline__ void load_edge(const void* ei, int nedges, int e,
                                          int& s, int& d) {
    if (g_idx64) {
        const long long* p = (const long long*)ei;
        s = (int)p[e];
        d = (int)p[(size_t)nedges + e];
    } else {
        const int* p = (const int*)ei;
        s = p[e];
        d = p[(size_t)nedges + e];
    }
}

// ---------------------------------------------------------------------------
// GEMM, DOUT=128: Y[n,c] = sum_k X[n,k] * W[k,c]
// Block: 128 threads, 32 rows per block. W fully resident in smem (64KB),
// X tile (32x128, 16KB) in smem. Each thread: 8 rows x 4 cols register tile.
// ---------------------------------------------------------------------------
__global__ void gemm128_kernel(const float* __restrict__ X,
                               const float* __restrict__ W,
                               float* __restrict__ Y, int nrows) {
    extern __shared__ float sm[];
    float* Ws = sm;                 // 128*128
    float* Xs = sm + 128 * 128;     // 32*128
    const int tid = threadIdx.x;

    const float4* W4 = (const float4*)W;
    float4* Ws4 = (float4*)Ws;
#pragma unroll
    for (int i = tid; i < 128 * 32; i += 128) Ws4[i] = W4[i];

    const int row0 = blockIdx.x * 32;
    const float4* X4 = (const float4*)X;
    float4* Xs4 = (float4*)Xs;
#pragma unroll
    for (int i = tid; i < 32 * 32; i += 128) {
        int gr = row0 + (i >> 5);
        Xs4[i] = (gr < nrows) ? X4[(size_t)gr * 32 + (i & 31)]
                              : make_float4(0.f, 0.f, 0.f, 0.f);
    }
    __syncthreads();

    const int cg = tid & 31;   // column group: cols 4*cg .. 4*cg+3
    const int rg = tid >> 5;   // row group (== warp id): rows 8*rg .. 8*rg+7

    float acc[8][4];
#pragma unroll
    for (int r = 0; r < 8; r++) {
        acc[r][0] = 0.f; acc[r][1] = 0.f; acc[r][2] = 0.f; acc[r][3] = 0.f;
    }
    const float* xbase = Xs + rg * 8 * 128;
    const float4* Wsv = (const float4*)Ws;

#pragma unroll 4
    for (int k = 0; k < 128; k++) {
        float4 w4 = Wsv[k * 32 + cg];
#pragma unroll
        for (int r = 0; r < 8; r++) {
            float x = xbase[r * 128 + k];
            acc[r][0] += x * w4.x;
            acc[r][1] += x * w4.y;
            acc[r][2] += x * w4.z;
            acc[r][3] += x * w4.w;
        }
    }

#pragma unroll
    for (int r = 0; r < 8; r++) {
        int gr = row0 + rg * 8 + r;
        if (gr < nrows) {
            ((float4*)Y)[(size_t)gr * 32 + cg] =
                make_float4(acc[r][0], acc[r][1], acc[r][2], acc[r][3]);
        }
    }
}

// ---------------------------------------------------------------------------
// GEMM, DOUT=40. Block: 256 threads, 32 rows per block.
// ---------------------------------------------------------------------------
__global__ void gemm40_kernel(const float* __restrict__ X,
                              const float* __restrict__ W,
                              float* __restrict__ Y, int nrows) {
    __shared__ float Ws[128 * DO];      // 20.5 KB
    __shared__ float Xs[32 * 128];      // 16 KB
    const int tid = threadIdx.x;

    for (int i = tid; i < 128 * DO; i += 256) Ws[i] = W[i];

    const int row0 = blockIdx.x * 32;
    const float4* X4 = (const float4*)X;
    float4* Xs4 = (float4*)Xs;
    for (int i = tid; i < 32 * 32; i += 256) {
        int gr = row0 + (i >> 5);
        Xs4[i] = (gr < nrows) ? X4[(size_t)gr * 32 + (i & 31)]
                              : make_float4(0.f, 0.f, 0.f, 0.f);
    }
    __syncthreads();

    const int c  = tid & 63;   // column (active if < 40)
    const int rg = tid >> 6;   // row group: rows 8*rg .. 8*rg+7
    if (c < DO) {
        float acc[8];
#pragma unroll
        for (int r = 0; r < 8; r++) acc[r] = 0.f;
        const float* xbase = Xs + rg * 8 * 128;
#pragma unroll 4
        for (int k = 0; k < 128; k++) {
            float wk = Ws[k * DO + c];
#pragma unroll
            for (int r = 0; r < 8; r++) acc[r] += xbase[r * 128 + k] * wk;
        }
#pragma unroll
        for (int r = 0; r < 8; r++) {
            int gr = row0 + rg * 8 + r;
            if (gr < nrows) Y[(size_t)gr * DO + c] = acc[r];
        }
    }
}

// ---------------------------------------------------------------------------
__global__ void zero_kernel(float4* __restrict__ p, int n4) {
    int i = blockIdx.x * blockDim.x + threadIdx.x;
    if (i < n4) p[i] = make_float4(0.f, 0.f, 0.f, 0.f);
}

// ---------------------------------------------------------------------------
// Scatter (D=128): one warp per edge. float4 gather of h[src], scale by
// edge weight, 4 scalar atomicAdds into agg[dst] per lane.
// ---------------------------------------------------------------------------
__global__ void scatter128_kernel(const void* __restrict__ ei,
                                  const float* __restrict__ ew,
                                  const float* __restrict__ H,
                                  float* __restrict__ agg, int nedges) {
    int e = blockIdx.x * 8 + (threadIdx.x >> 5);
    if (e >= nedges) return;
    const int lane = threadIdx.x & 31;
    int s, d;
    load_edge(ei, nedges, e, s, d);
    float wt = ew[e];
    float4 v = ((const float4*)(H + (size_t)s * 128))[lane];
    float* a = agg + (size_t)d * 128 + lane * 4;
    atomicAdd(a + 0, v.x * wt);
    atomicAdd(a + 1, v.y * wt);
    atomicAdd(a + 2, v.z * wt);
    atomicAdd(a + 3, v.w * wt);
}

// ---------------------------------------------------------------------------
// Scatter (D=40): one warp per edge.
// ---------------------------------------------------------------------------
__global__ void scatter40_kernel(const void* __restrict__ ei,
                                 const float* __restrict__ ew,
                                 const float* __restrict__ H,
                                 float* __restrict__ agg, int nedges) {
    int e = blockIdx.x * 8 + (threadIdx.x >> 5);
    if (e >= nedges) return;
    const int lane = threadIdx.x & 31;
    int s, d;
    load_edge(ei, nedges, e, s, d);
    float wt = ew[e];
    const float* hs = H + (size_t)s * DO;
    float* a = agg + (size_t)d * DO;
    atomicAdd(a + lane, hs[lane] * wt);
    if (lane < 8) atomicAdd(a + 32 + lane, hs[32 + lane] * wt);
}

// ---------------------------------------------------------------------------
__global__ void bias_relu128_kernel(float4* __restrict__ y,
                                    const float4* __restrict__ b, int n4) {
    int i = blockIdx.x * blockDim.x + threadIdx.x;
    if (i < n4) {
        float4 v = y[i];
        float4 bb = b[i & 31];
        v.x = fmaxf(v.x + bb.x, 0.f);
        v.y = fmaxf(v.y + bb.y, 0.f);
        v.z = fmaxf(v.z + bb.z, 0.f);
        v.w = fmaxf(v.w + bb.w, 0.f);
        y[i] = v;
    }
}

// ---------------------------------------------------------------------------
// Bias + log_softmax over 40 classes: one warp per node.
// ---------------------------------------------------------------------------
__global__ void lsm_kernel(const float* __restrict__ agg,
                           const float* __restrict__ b,
                           float* __restrict__ out, int n) {
    int node = blockIdx.x * 8 + (threadIdx.x >> 5);
    if (node >= n) return;
    const int lane = threadIdx.x & 31;
    const float* a = agg + (size_t)node * DO;

    float v0 = a[lane] + b[lane];
    float v1 = (lane < 8) ? (a[32 + lane] + b[32 + lane]) : -1e30f;

    float m = fmaxf(v0, v1);
#pragma unroll
    for (int o = 16; o; o >>= 1) m = fmaxf(m, __shfl_xor_sync(0xffffffffu, m, o));

    float sum = __expf(v0 - m) + ((lane < 8) ? __expf(v1 - m) : 0.f);
#pragma unroll
    for (int o = 16; o; o >>= 1) sum += __shfl_xor_sync(0xffffffffu, sum, o);

    float lse = m + __logf(sum);
    out[(size_t)node * DO + lane] = v0 - lse;
    if (lane < 8) out[(size_t)node * DO + 32 + lane] = v1 - lse;
}

// ---------------------------------------------------------------------------
extern "C" void kernel_launch(void* const* d_in, const int* in_sizes, int n_in,
                              void* d_out, int out_size) {
    const float* x  = (const float*)d_in[0];
    const void*  ei = d_in[1];
    const float* ew = (const float*)d_in[2];
    const float* W1 = (const float*)d_in[3];
    const float* b1 = (const float*)d_in[4];
    const float* W2 = (const float*)d_in[5];
    const float* b2 = (const float*)d_in[6];
    const float* W3 = (const float*)d_in[7];
    const float* b3 = (const float*)d_in[8];
    float* out = (float*)d_out;

    const int n  = in_sizes[0] / DH;   // 100000 nodes
    const int ne = in_sizes[1] / 2;    // 1.6M edges
    (void)n_in; (void)out_size;

    float *A, *B;
    cudaGetSymbolAddress((void**)&A, g_bufA);
    cudaGetSymbolAddress((void**)&B, g_bufB);

    const int SMEM128 = (128 * 128 + 32 * 128) * (int)sizeof(float); // 80 KB
    cudaFuncSetAttribute(gemm128_kernel,
                         cudaFuncAttributeMaxDynamicSharedMemorySize, SMEM128);

    const int gemmBlocks = (n + 31) / 32;
    const int edgeBlocks = (ne + 7) / 8;
    const int n4_128 = n * 32;   // N*128/4 float4
    const int n4_40  = n * 10;   // N*40/4  float4

    detect_idx_kernel<<<1, 1>>>(ei, n);

    // ---- layer 1 ----
    gemm128_kernel<<<gemmBlocks, 128, SMEM128>>>(x, W1, A, n);
    zero_kernel<<<(n4_128 + 255) / 256, 256>>>((float4*)B, n4_128);
    scatter128_kernel<<<edgeBlocks, 256>>>(ei, ew, A, B, ne);
    bias_relu128_kernel<<<(n4_128 + 255) / 256, 256>>>((float4*)B,
                                                       (const float4*)b1, n4_128);
    // ---- layer 2 ----
    gemm128_kernel<<<gemmBlocks, 128, SMEM128>>>(B, W2, A, n);
    zero_kernel<<<(n4_128 + 255) / 256, 256>>>((float4*)B, n4_128);
    scatter128_kernel<<<edgeBlocks, 256>>>(ei, ew, A, B, ne);
    bias_relu128_kernel<<<(n4_128 + 255) / 256, 256>>>((float4*)B,
                                                       (const float4*)b2, n4_128);
    // ---- layer 3 (D_OUT = 40) ----
    gemm40_kernel<<<gemmBlocks, 256>>>(B, W3, A, n);     // A used as N x 40
    zero_kernel<<<(n4_40 + 255) / 256, 256>>>((float4*)B, n4_40);
    scatter40_kernel<<<edgeBlocks, 256>>>(ei, ew, A, B, ne);
    lsm_kernel<<<(n + 7) / 8, 256>>>(B, b3, out, n);
}

// round 3
// speedup vs baseline: 2.4932x; 2.4932x over previous
#include <cuda_runtime.h>
#include <cstdint>

// ---------------------------------------------------------------------------
// AdjGCN: 3-layer GCN forward, CSR-gather aggregation (no float atomics).
// Per replay: build dst-CSR (count, scan, fill), then per layer:
//   h = X @ W  (smem-tiled SIMT GEMM)
//   agg[v] = sum_{e: dst=v} h[src_e] * w_e   (warp-per-node gather)
//   + bias (+ReLU) fused into the gather epilogue; final layer fuses
//   log_softmax.
// ---------------------------------------------------------------------------

#define MAXN 100000
#define MAXE 1600000
#define DH   128
#define DO   40

__device__ float g_bufA[(size_t)MAXN * DH];
__device__ float g_bufB[(size_t)MAXN * DH];
__device__ int   g_idx64;            // 1 if edge_index is int64, 0 if int32
__device__ int   g_rowptr[MAXN + 1];
__device__ int   g_deg[MAXN];
__device__ int   g_fill[MAXN];
__device__ int   g_esrc[MAXE];
__device__ float g_ews[MAXE];
__device__ int   g_partials[128];

// ---------------------------------------------------------------------------
__global__ void detect_idx_kernel(const void* ei, int n_nodes) {
    const long long* p = (const long long*)ei;
    int ok64 = 1;
    for (int i = 0; i < 32; i++) {
        long long v = p[i];
        if (v < 0 || v >= n_nodes) { ok64 = 0; break; }
    }
    g_idx64 = ok64;
}

__device__ __forceinline__ void load_edge(const void* ei, int nedges, int e,
                                          int& s, int& d) {
    if (g_idx64) {
        const long long* p = (const long long*)ei;
        s = (int)p[e];
        d = (int)p[(size_t)nedges + e];
    } else {
        const int* p = (const int*)ei;
        s = p[e];
        d = p[(size_t)nedges + e];
    }
}

// ------------------------------ CSR build ---------------------------------
__global__ void deg_zero_kernel(int* __restrict__ deg, int n) {
    int i = blockIdx.x * blockDim.x + threadIdx.x;
    if (i < n) deg[i] = 0;
}

__global__ void deg_count_kernel(const void* __restrict__ ei, int ne,
                                 int* __restrict__ deg) {
    int e = blockIdx.x * blockDim.x + threadIdx.x;
    if (e < ne) {
        int s, d;
        load_edge(ei, ne, e, s, d);
        atomicAdd(&deg[d], 1);
    }
}

// Block-local exclusive scan over chunks of 1024; block total -> partials.
__global__ void scan_block_kernel(const int* __restrict__ deg,
                                  int* __restrict__ rowptr,
                                  int* __restrict__ partials, int n) {
    __shared__ int sm[1024];
    const int tid = threadIdx.x;
    int i = blockIdx.x * 1024 + tid;
    int v = (i < n) ? deg[i] : 0;
    sm[tid] = v;
    __syncthreads();
#pragma unroll
    for (int o = 1; o < 1024; o <<= 1) {
        int t = (tid >= o) ? sm[tid - o] : 0;
        __syncthreads();
        sm[tid] += t;
        __syncthreads();
    }
    if (i < n) rowptr[i] = sm[tid] - v;           // exclusive within block
    if (tid == 1023) partials[blockIdx.x] = sm[1023];
}

// Exclusive scan of per-block totals (nb <= 128) in a single block.
__global__ void scan_partials_kernel(int* __restrict__ partials, int nb) {
    __shared__ int sm[128];
    const int tid = threadIdx.x;
    int v = (tid < nb) ? partials[tid] : 0;
    sm[tid] = v;
    __syncthreads();
#pragma unroll
    for (int o = 1; o < 128; o <<= 1) {
        int t = (tid >= o) ? sm[tid - o] : 0;
        __syncthreads();
        sm[tid] += t;
        __syncthreads();
    }
    if (tid < nb) partials[tid] = sm[tid] - v;    // exclusive
}

__global__ void scan_add_kernel(int* __restrict__ rowptr,
                                const int* __restrict__ partials,
                                int* __restrict__ fill, int n, int ne) {
    int i = blockIdx.x * blockDim.x + threadIdx.x;
    if (i < n) {
        int v = rowptr[i] + partials[i >> 10];
        rowptr[i] = v;
        fill[i] = v;
    }
    if (i == 0) rowptr[n] = ne;
}

__global__ void csr_fill_kernel(const void* __restrict__ ei,
                                const float* __restrict__ ew, int ne,
                                int* __restrict__ fill,
                                int* __restrict__ esrc,
                                float* __restrict__ ews) {
    int e = blockIdx.x * blockDim.x + threadIdx.x;
    if (e < ne) {
        int s, d;
        load_edge(ei, ne, e, s, d);
        int pos = atomicAdd(&fill[d], 1);
        esrc[pos] = s;
        ews[pos] = ew[e];
    }
}

// ------------------------------ GEMMs -------------------------------------
__global__ void gemm128_kernel(const float* __restrict__ X,
                               const float* __restrict__ W,
                               float* __restrict__ Y, int nrows) {
    extern __shared__ float sm[];
    float* Ws = sm;                 // 128*128
    float* Xs = sm + 128 * 128;     // 32*128
    const int tid = threadIdx.x;

    const float4* W4 = (const float4*)W;
    float4* Ws4 = (float4*)Ws;
#pragma unroll
    for (int i = tid; i < 128 * 32; i += 128) Ws4[i] = W4[i];

    const int row0 = blockIdx.x * 32;
    const float4* X4 = (const float4*)X;
    float4* Xs4 = (float4*)Xs;
#pragma unroll
    for (int i = tid; i < 32 * 32; i += 128) {
        int gr = row0 + (i >> 5);
        Xs4[i] = (gr < nrows) ? X4[(size_t)gr * 32 + (i & 31)]
                              : make_float4(0.f, 0.f, 0.f, 0.f);
    }
    __syncthreads();

    const int cg = tid & 31;
    const int rg = tid >> 5;

    float acc[8][4];
#pragma unroll
    for (int r = 0; r < 8; r++) {
        acc[r][0] = 0.f; acc[r][1] = 0.f; acc[r][2] = 0.f; acc[r][3] = 0.f;
    }
    const float* xbase = Xs + rg * 8 * 128;
    const float4* Wsv = (const float4*)Ws;

#pragma unroll 4
    for (int k = 0; k < 128; k++) {
        float4 w4 = Wsv[k * 32 + cg];
#pragma unroll
        for (int r = 0; r < 8; r++) {
            float x = xbase[r * 128 + k];
            acc[r][0] += x * w4.x;
            acc[r][1] += x * w4.y;
            acc[r][2] += x * w4.z;
            acc[r][3] += x * w4.w;
        }
    }

#pragma unroll
    for (int r = 0; r < 8; r++) {
        int gr = row0 + rg * 8 + r;
        if (gr < nrows) {
            ((float4*)Y)[(size_t)gr * 32 + cg] =
                make_float4(acc[r][0], acc[r][1], acc[r][2], acc[r][3]);
        }
    }
}

__global__ void gemm40_kernel(const float* __restrict__ X,
                              const float* __restrict__ W,
                              float* __restrict__ Y, int nrows) {
    __shared__ float Ws[128 * DO];
    __shared__ float Xs[32 * 128];
    const int tid = threadIdx.x;

    for (int i = tid; i < 128 * DO; i += 256) Ws[i] = W[i];

    const int row0 = blockIdx.x * 32;
    const float4* X4 = (const float4*)X;
    float4* Xs4 = (float4*)Xs;
    for (int i = tid; i < 32 * 32; i += 256) {
        int gr = row0 + (i >> 5);
        Xs4[i] = (gr < nrows) ? X4[(size_t)gr * 32 + (i & 31)]
                              : make_float4(0.f, 0.f, 0.f, 0.f);
    }
    __syncthreads();

    const int c  = tid & 63;
    const int rg = tid >> 6;
    if (c < DO) {
        float acc[8];
#pragma unroll
        for (int r = 0; r < 8; r++) acc[r] = 0.f;
        const float* xbase = Xs + rg * 8 * 128;
#pragma unroll 4
        for (int k = 0; k < 128; k++) {
            float wk = Ws[k * DO + c];
#pragma unroll
            for (int r = 0; r < 8; r++) acc[r] += xbase[r * 128 + k] * wk;
        }
#pragma unroll
        for (int r = 0; r < 8; r++) {
            int gr = row0 + rg * 8 + r;
            if (gr < nrows) Y[(size_t)gr * DO + c] = acc[r];
        }
    }
}

// ----------------------- CSR gather aggregation ----------------------------
// D=128: one warp per node, lane owns float4 column chunk. Fused bias+ReLU.
__global__ void agg128_kernel(const int* __restrict__ rowptr,
                              const int* __restrict__ esrc,
                              const float* __restrict__ ews,
                              const float* __restrict__ H,
                              const float* __restrict__ bias,
                              float* __restrict__ Y, int n) {
    int node = blockIdx.x * 8 + (threadIdx.x >> 5);
    if (node >= n) return;
    const int lane = threadIdx.x & 31;
    int beg = rowptr[node];
    int end = rowptr[node + 1];

    float4 acc = make_float4(0.f, 0.f, 0.f, 0.f);
    int j = beg;
    // unroll by 2 for MLP
    for (; j + 1 < end; j += 2) {
        int s0 = esrc[j];     float w0 = ews[j];
        int s1 = esrc[j + 1]; float w1 = ews[j + 1];
        float4 v0 = ((const float4*)(H + (size_t)s0 * 128))[lane];
        float4 v1 = ((const float4*)(H + (size_t)s1 * 128))[lane];
        acc.x += v0.x * w0 + v1.x * w1;
        acc.y += v0.y * w0 + v1.y * w1;
        acc.z += v0.z * w0 + v1.z * w1;
        acc.w += v0.w * w0 + v1.w * w1;
    }
    if (j < end) {
        int s = esrc[j]; float w = ews[j];
        float4 v = ((const float4*)(H + (size_t)s * 128))[lane];
        acc.x += v.x * w; acc.y += v.y * w; acc.z += v.z * w; acc.w += v.w * w;
    }

    float4 b = ((const float4*)bias)[lane];
    acc.x = fmaxf(acc.x + b.x, 0.f);
    acc.y = fmaxf(acc.y + b.y, 0.f);
    acc.z = fmaxf(acc.z + b.z, 0.f);
    acc.w = fmaxf(acc.w + b.w, 0.f);
    ((float4*)(Y + (size_t)node * 128))[lane] = acc;
}

// D=40 gather + bias + log_softmax, one warp per node.
__global__ void agg40_lsm_kernel(const int* __restrict__ rowptr,
                                 const int* __restrict__ esrc,
                                 const float* __restrict__ ews,
                                 const float* __restrict__ H,
                                 const float* __restrict__ b,
                                 float* __restrict__ out, int n) {
    int node = blockIdx.x * 8 + (threadIdx.x >> 5);
    if (node >= n) return;
    const int lane = threadIdx.x & 31;
    int beg = rowptr[node];
    int end = rowptr[node + 1];

    float a0 = 0.f, a1 = 0.f;
    for (int j = beg; j < end; j++) {
        int s = esrc[j]; float w = ews[j];
        const float* hs = H + (size_t)s * DO;
        a0 += hs[lane] * w;
        if (lane < 8) a1 += hs[32 + lane] * w;
    }

    float v0 = a0 + b[lane];
    float v1 = (lane < 8) ? (a1 + b[32 + lane]) : -1e30f;

    float m = fmaxf(v0, v1);
#pragma unroll
    for (int o = 16; o; o >>= 1) m = fmaxf(m, __shfl_xor_sync(0xffffffffu, m, o));

    float sum = __expf(v0 - m) + ((lane < 8) ? __expf(v1 - m) : 0.f);
#pragma unroll
    for (int o = 16; o; o >>= 1) sum += __shfl_xor_sync(0xffffffffu, sum, o);

    float lse = m + __logf(sum);
    out[(size_t)node * DO + lane] = v0 - lse;
    if (lane < 8) out[(size_t)node * DO + 32 + lane] = v1 - lse;
}

// ---------------------------------------------------------------------------
extern "C" void kernel_launch(void* const* d_in, const int* in_sizes, int n_in,
                              void* d_out, int out_size) {
    const float* x  = (const float*)d_in[0];
    const void*  ei = d_in[1];
    const float* ew = (const float*)d_in[2];
    const float* W1 = (const float*)d_in[3];
    const float* b1 = (const float*)d_in[4];
    const float* W2 = (const float*)d_in[5];
    const float* b2 = (const float*)d_in[6];
    const float* W3 = (const float*)d_in[7];
    const float* b3 = (const float*)d_in[8];
    float* out = (float*)d_out;

    const int n  = in_sizes[0] / DH;   // 100000 nodes
    int ne = in_sizes[1] / 2;          // 1.6M edges
    if (ne > MAXE) ne = MAXE;
    (void)n_in; (void)out_size;

    float *A, *B;
    int *rowptr, *deg, *fill, *esrc, *partials;
    float* ews;
    cudaGetSymbolAddress((void**)&A, g_bufA);
    cudaGetSymbolAddress((void**)&B, g_bufB);
    cudaGetSymbolAddress((void**)&rowptr, g_rowptr);
    cudaGetSymbolAddress((void**)&deg, g_deg);
    cudaGetSymbolAddress((void**)&fill, g_fill);
    cudaGetSymbolAddress((void**)&esrc, g_esrc);
    cudaGetSymbolAddress((void**)&ews, g_ews);
    cudaGetSymbolAddress((void**)&partials, g_partials);

    const int SMEM128 = (128 * 128 + 32 * 128) * (int)sizeof(float); // 80 KB
    cudaFuncSetAttribute(gemm128_kernel,
                         cudaFuncAttributeMaxDynamicSharedMemorySize, SMEM128);

    const int gemmBlocks = (n + 31) / 32;
    const int nodeWarpBlocks = (n + 7) / 8;
    const int scanBlocks = (n + 1023) / 1024;   // 98 for n=100000

    detect_idx_kernel<<<1, 1>>>(ei, n);

    // ---- CSR build (by dst) ----
    deg_zero_kernel<<<(n + 255) / 256, 256>>>(deg, n);
    deg_count_kernel<<<(ne + 255) / 256, 256>>>(ei, ne, deg);
    scan_block_kernel<<<scanBlocks, 1024>>>(deg, rowptr, partials, n);
    scan_partials_kernel<<<1, 128>>>(partials, scanBlocks);
    scan_add_kernel<<<(n + 255) / 256, 256>>>(rowptr, partials, fill, n, ne);
    csr_fill_kernel<<<(ne + 255) / 256, 256>>>(ei, ew, ne, fill, esrc, ews);

    // ---- layer 1 ----
    gemm128_kernel<<<gemmBlocks, 128, SMEM128>>>(x, W1, A, n);
    agg128_kernel<<<nodeWarpBlocks, 256>>>(rowptr, esrc, ews, A, b1, B, n);
    // ---- layer 2 ----
    gemm128_kernel<<<gemmBlocks, 128, SMEM128>>>(B, W2, A, n);
    agg128_kernel<<<nodeWarpBlocks, 256>>>(rowptr, esrc, ews, A, b2, B, n);
    // ---- layer 3 (D_OUT = 40) ----
    gemm40_kernel<<<gemmBlocks, 256>>>(B, W3, A, n);     // A used as N x 40
    agg40_lsm_kernel<<<nodeWarpBlocks, 256>>>(rowptr, esrc, ews, A, b3, out, n);
}

// round 4
// speedup vs baseline: 2.6354x; 1.0571x over previous
#include <cuda_runtime.h>
#include <cstdint>

// ---------------------------------------------------------------------------
// AdjGCN: 3-layer GCN forward, CSR-gather aggregation (no float atomics).
// ---------------------------------------------------------------------------

#define MAXN 100000
#define MAXE 1600000
#define DH   128
#define DO   40

__device__ float g_bufA[(size_t)MAXN * DH];
__device__ float g_bufB[(size_t)MAXN * DH];
__device__ int   g_idx64;            // 1 if edge_index is int64, 0 if int32
__device__ int   g_rowptr[MAXN + 1];
__device__ int   g_deg[MAXN];
__device__ int   g_fill[MAXN];
__device__ int   g_esrc[MAXE];
__device__ float g_ews[MAXE];
__device__ int   g_partials[128];

// ---------------------------------------------------------------------------
__device__ __forceinline__ void load_edge(const void* ei, int nedges, int e,
                                          int& s, int& d) {
    if (g_idx64) {
        const long long* p = (const long long*)ei;
        s = (int)p[e];
        d = (int)p[(size_t)nedges + e];
    } else {
        const int* p = (const int*)ei;
        s = p[e];
        d = p[(size_t)nedges + e];
    }
}

// ------------------------------ CSR build ---------------------------------
// Zero degrees; block 0/thread 0 also probes the edge_index dtype.
__global__ void deg_zero_kernel(int* __restrict__ deg, int n,
                                const void* ei, int n_nodes) {
    int i = blockIdx.x * blockDim.x + threadIdx.x;
    if (i < n) deg[i] = 0;
    if (blockIdx.x == 0 && threadIdx.x == 0) {
        const long long* p = (const long long*)ei;
        int ok64 = 1;
        for (int k = 0; k < 32; k++) {
            long long v = p[k];
            if (v < 0 || v >= n_nodes) { ok64 = 0; break; }
        }
        g_idx64 = ok64;
    }
}

__global__ void deg_count_kernel(const void* __restrict__ ei, int ne,
                                 int* __restrict__ deg) {
    int e = blockIdx.x * blockDim.x + threadIdx.x;
    if (e < ne) {
        int s, d;
        load_edge(ei, ne, e, s, d);
        atomicAdd(&deg[d], 1);
    }
}

__global__ void scan_block_kernel(const int* __restrict__ deg,
                                  int* __restrict__ rowptr,
                                  int* __restrict__ partials, int n) {
    __shared__ int sm[1024];
    const int tid = threadIdx.x;
    int i = blockIdx.x * 1024 + tid;
    int v = (i < n) ? deg[i] : 0;
    sm[tid] = v;
    __syncthreads();
#pragma unroll
    for (int o = 1; o < 1024; o <<= 1) {
        int t = (tid >= o) ? sm[tid - o] : 0;
        __syncthreads();
        sm[tid] += t;
        __syncthreads();
    }
    if (i < n) rowptr[i] = sm[tid] - v;
    if (tid == 1023) partials[blockIdx.x] = sm[1023];
}

__global__ void scan_partials_kernel(int* __restrict__ partials, int nb) {
    __shared__ int sm[128];
    const int tid = threadIdx.x;
    int v = (tid < nb) ? partials[tid] : 0;
    sm[tid] = v;
    __syncthreads();
#pragma unroll
    for (int o = 1; o < 128; o <<= 1) {
        int t = (tid >= o) ? sm[tid - o] : 0;
        __syncthreads();
        sm[tid] += t;
        __syncthreads();
    }
    if (tid < nb) partials[tid] = sm[tid] - v;
}

__global__ void scan_add_kernel(int* __restrict__ rowptr,
                                const int* __restrict__ partials,
                                int* __restrict__ fill, int n, int ne) {
    int i = blockIdx.x * blockDim.x + threadIdx.x;
    if (i < n) {
        int v = rowptr[i] + partials[i >> 10];
        rowptr[i] = v;
        fill[i] = v;
    }
    if (i == 0) rowptr[n] = ne;
}

__global__ void csr_fill_kernel(const void* __restrict__ ei,
                                const float* __restrict__ ew, int ne,
                                int* __restrict__ fill,
                                int* __restrict__ esrc,
                                float* __restrict__ ews) {
    int e = blockIdx.x * blockDim.x + threadIdx.x;
    if (e < ne) {
        int s, d;
        load_edge(ei, ne, e, s, d);
        int pos = atomicAdd(&fill[d], 1);
        esrc[pos] = s;
        ews[pos] = ew[e];
    }
}

// ------------------------------ GEMMs -------------------------------------
// 128x128 W resident in smem; 32 rows/block, 128 threads; 8 rows x 4 cols
// register tile per thread; float4-over-k loads (12 LDS per 128 FMA).
__global__ void gemm128_kernel(const float* __restrict__ X,
                               const float* __restrict__ W,
                               float* __restrict__ Y, int nrows) {
    extern __shared__ float sm[];
    float* Ws = sm;                 // 128*128
    float* Xs = sm + 128 * 128;     // 32*128
    const int tid = threadIdx.x;

    const float4* W4 = (const float4*)W;
    float4* Ws4 = (float4*)Ws;
#pragma unroll
    for (int i = tid; i < 128 * 32; i += 128) Ws4[i] = W4[i];

    const int row0 = blockIdx.x * 32;
    const float4* X4 = (const float4*)X;
    float4* Xs4 = (float4*)Xs;
#pragma unroll
    for (int i = tid; i < 32 * 32; i += 128) {
        int gr = row0 + (i >> 5);
        Xs4[i] = (gr < nrows) ? X4[(size_t)gr * 32 + (i & 31)]
                              : make_float4(0.f, 0.f, 0.f, 0.f);
    }
    __syncthreads();

    const int cg = tid & 31;
    const int rg = tid >> 5;

    float acc[8][4];
#pragma unroll
    for (int r = 0; r < 8; r++) {
        acc[r][0] = 0.f; acc[r][1] = 0.f; acc[r][2] = 0.f; acc[r][3] = 0.f;
    }
    const float4* xb4 = (const float4*)(Xs + rg * 8 * 128);
    const float4* Wsv = (const float4*)Ws;

#pragma unroll 4
    for (int k4 = 0; k4 < 32; k4++) {
        float4 xv[8];
#pragma unroll
        for (int r = 0; r < 8; r++) xv[r] = xb4[r * 32 + k4];
        float4 w0 = Wsv[(4 * k4 + 0) * 32 + cg];
        float4 w1 = Wsv[(4 * k4 + 1) * 32 + cg];
        float4 w2 = Wsv[(4 * k4 + 2) * 32 + cg];
        float4 w3 = Wsv[(4 * k4 + 3) * 32 + cg];
#pragma unroll
        for (int r = 0; r < 8; r++) {
            acc[r][0] += xv[r].x * w0.x + xv[r].y * w1.x
                       + xv[r].z * w2.x + xv[r].w * w3.x;
            acc[r][1] += xv[r].x * w0.y + xv[r].y * w1.y
                       + xv[r].z * w2.y + xv[r].w * w3.y;
            acc[r][2] += xv[r].x * w0.z + xv[r].y * w1.z
                       + xv[r].z * w2.z + xv[r].w * w3.z;
            acc[r][3] += xv[r].x * w0.w + xv[r].y * w1.w
                       + xv[r].z * w2.w + xv[r].w * w3.w;
        }
    }

#pragma unroll
    for (int r = 0; r < 8; r++) {
        int gr = row0 + rg * 8 + r;
        if (gr < nrows) {
            ((float4*)Y)[(size_t)gr * 32 + cg] =
                make_float4(acc[r][0], acc[r][1], acc[r][2], acc[r][3]);
        }
    }
}

// D_OUT=40: 320 threads (8 row-groups x 40 cols, all lanes active),
// 64 rows/block, float4-over-k loads.
__global__ void gemm40_kernel(const float* __restrict__ X,
                              const float* __restrict__ W,
                              float* __restrict__ Y, int nrows) {
    extern __shared__ float sm[];
    float* Ws = sm;                 // 128*40
    float* Xs = sm + 128 * DO;      // 64*128
    const int tid = threadIdx.x;

    for (int i = tid; i < 128 * DO; i += 320) Ws[i] = W[i];

    const int row0 = blockIdx.x * 64;
    const float4* X4 = (const float4*)X;
    float4* Xs4 = (float4*)Xs;
    for (int i = tid; i < 64 * 32; i += 320) {
        int gr = row0 + (i >> 5);
        Xs4[i] = (gr < nrows) ? X4[(size_t)gr * 32 + (i & 31)]
                              : make_float4(0.f, 0.f, 0.f, 0.f);
    }
    __syncthreads();

    const int c  = tid % DO;
    const int rg = tid / DO;    // 0..7
    float acc[8];
#pragma unroll
    for (int r = 0; r < 8; r++) acc[r] = 0.f;
    const float4* xb4 = (const float4*)(Xs + rg * 8 * 128);

#pragma unroll 4
    for (int k4 = 0; k4 < 32; k4++) {
        float w0 = Ws[(4 * k4 + 0) * DO + c];
        float w1 = Ws[(4 * k4 + 1) * DO + c];
        float w2 = Ws[(4 * k4 + 2) * DO + c];
        float w3 = Ws[(4 * k4 + 3) * DO + c];
#pragma unroll
        for (int r = 0; r < 8; r++) {
            float4 xv = xb4[r * 32 + k4];
            acc[r] += xv.x * w0 + xv.y * w1 + xv.z * w2 + xv.w * w3;
        }
    }
#pragma unroll
    for (int r = 0; r < 8; r++) {
        int gr = row0 + rg * 8 + r;
        if (gr < nrows) Y[(size_t)gr * DO + c] = acc[r];
    }
}

// ----------------------- CSR gather aggregation ----------------------------
__global__ void agg128_kernel(const int* __restrict__ rowptr,
                              const int* __restrict__ esrc,
                              const float* __restrict__ ews,
                              const float* __restrict__ H,
                              const float* __restrict__ bias,
                              float* __restrict__ Y, int n) {
    int node = blockIdx.x * 8 + (threadIdx.x >> 5);
    if (node >= n) return;
    const int lane = threadIdx.x & 31;
    int beg = rowptr[node];
    int end = rowptr[node + 1];

    float4 acc = make_float4(0.f, 0.f, 0.f, 0.f);
    int j = beg;
    for (; j + 3 < end; j += 4) {
        int s0 = esrc[j];     float w0 = ews[j];
        int s1 = esrc[j + 1]; float w1 = ews[j + 1];
        int s2 = esrc[j + 2]; float w2 = ews[j + 2];
        int s3 = esrc[j + 3]; float w3 = ews[j + 3];
        float4 v0 = ((const float4*)(H + (size_t)s0 * 128))[lane];
        float4 v1 = ((const float4*)(H + (size_t)s1 * 128))[lane];
        float4 v2 = ((const float4*)(H + (size_t)s2 * 128))[lane];
        float4 v3 = ((const float4*)(H + (size_t)s3 * 128))[lane];
        acc.x += v0.x * w0 + v1.x * w1 + v2.x * w2 + v3.x * w3;
        acc.y += v0.y * w0 + v1.y * w1 + v2.y * w2 + v3.y * w3;
        acc.z += v0.z * w0 + v1.z * w1 + v2.z * w2 + v3.z * w3;
        acc.w += v0.w * w0 + v1.w * w1 + v2.w * w2 + v3.w * w3;
    }
    for (; j < end; j++) {
        int s = esrc[j]; float w = ews[j];
        float4 v = ((const float4*)(H + (size_t)s * 128))[lane];
        acc.x += v.x * w; acc.y += v.y * w; acc.z += v.z * w; acc.w += v.w * w;
    }

    float4 b = ((const float4*)bias)[lane];
    acc.x = fmaxf(acc.x + b.x, 0.f);
    acc.y = fmaxf(acc.y + b.y, 0.f);
    acc.z = fmaxf(acc.z + b.z, 0.f);
    acc.w = fmaxf(acc.w + b.w, 0.f);
    ((float4*)(Y + (size_t)node * 128))[lane] = acc;
}

// D=40 gather + bias + log_softmax, one warp per node.
__global__ void agg40_lsm_kernel(const int* __restrict__ rowptr,
                                 const int* __restrict__ esrc,
                                 const float* __restrict__ ews,
                                 const float* __restrict__ H,
                                 const float* __restrict__ b,
                                 float* __restrict__ out, int n) {
    int node = blockIdx.x * 8 + (threadIdx.x >> 5);
    if (node >= n) return;
    const int lane = threadIdx.x & 31;
    int beg = rowptr[node];
    int end = rowptr[node + 1];

    float a0 = 0.f, a1 = 0.f;
    int j = beg;
    for (; j + 1 < end; j += 2) {
        int s0 = esrc[j];     float w0 = ews[j];
        int s1 = esrc[j + 1]; float w1 = ews[j + 1];
        const float* h0 = H + (size_t)s0 * DO;
        const float* h1 = H + (size_t)s1 * DO;
        a0 += h0[lane] * w0 + h1[lane] * w1;
        if (lane < 8) a1 += h0[32 + lane] * w0 + h1[32 + lane] * w1;
    }
    if (j < end) {
        int s = esrc[j]; float w = ews[j];
        const float* hs = H + (size_t)s * DO;
        a0 += hs[lane] * w;
        if (lane < 8) a1 += hs[32 + lane] * w;
    }

    float v0 = a0 + b[lane];
    float v1 = (lane < 8) ? (a1 + b[32 + lane]) : -1e30f;

    float m = fmaxf(v0, v1);
#pragma unroll
    for (int o = 16; o; o >>= 1) m = fmaxf(m, __shfl_xor_sync(0xffffffffu, m, o));

    float sum = __expf(v0 - m) + ((lane < 8) ? __expf(v1 - m) : 0.f);
#pragma unroll
    for (int o = 16; o; o >>= 1) sum += __shfl_xor_sync(0xffffffffu, sum, o);

    float lse = m + __logf(sum);
    out[(size_t)node * DO + lane] = v0 - lse;
    if (lane < 8) out[(size_t)node * DO + 32 + lane] = v1 - lse;
}

// ---------------------------------------------------------------------------
extern "C" void kernel_launch(void* const* d_in, const int* in_sizes, int n_in,
                              void* d_out, int out_size) {
    const float* x  = (const float*)d_in[0];
    const void*  ei = d_in[1];
    const float* ew = (const float*)d_in[2];
    const float* W1 = (const float*)d_in[3];
    const float* b1 = (const float*)d_in[4];
    const float* W2 = (const float*)d_in[5];
    const float* b2 = (const float*)d_in[6];
    const float* W3 = (const float*)d_in[7];
    const float* b3 = (const float*)d_in[8];
    float* out = (float*)d_out;

    const int n  = in_sizes[0] / DH;
    int ne = in_sizes[1] / 2;
    if (ne > MAXE) ne = MAXE;
    (void)n_in; (void)out_size;

    float *A, *B;
    int *rowptr, *deg, *fill, *esrc, *partials;
    float* ews;
    cudaGetSymbolAddress((void**)&A, g_bufA);
    cudaGetSymbolAddress((void**)&B, g_bufB);
    cudaGetSymbolAddress((void**)&rowptr, g_rowptr);
    cudaGetSymbolAddress((void**)&deg, g_deg);
    cudaGetSymbolAddress((void**)&fill, g_fill);
    cudaGetSymbolAddress((void**)&esrc, g_esrc);
    cudaGetSymbolAddress((void**)&ews, g_ews);
    cudaGetSymbolAddress((void**)&partials, g_partials);

    const int SMEM128 = (128 * 128 + 32 * 128) * (int)sizeof(float); // 80 KB
    const int SMEM40  = (128 * DO + 64 * 128) * (int)sizeof(float);  // 52 KB
    cudaFuncSetAttribute(gemm128_kernel,
                         cudaFuncAttributeMaxDynamicSharedMemorySize, SMEM128);
    cudaFuncSetAttribute(gemm40_kernel,
                         cudaFuncAttributeMaxDynamicSharedMemorySize, SMEM40);

    const int gemmBlocks   = (n + 31) / 32;
    const int gemm40Blocks = (n + 63) / 64;
    const int nodeWarpBlocks = (n + 7) / 8;
    const int scanBlocks = (n + 1023) / 1024;

    // ---- CSR build (by dst) ----
    deg_zero_kernel<<<(n + 255) / 256, 256>>>(deg, n, ei, n);
    deg_count_kernel<<<(ne + 255) / 256, 256>>>(ei, ne, deg);
    scan_block_kernel<<<scanBlocks, 1024>>>(deg, rowptr, partials, n);
    scan_partials_kernel<<<1, 128>>>(partials, scanBlocks);
    scan_add_kernel<<<(n + 255) / 256, 256>>>(rowptr, partials, fill, n, ne);
    csr_fill_kernel<<<(ne + 255) / 256, 256>>>(ei, ew, ne, fill, esrc, ews);

    // ---- layer 1 ----
    gemm128_kernel<<<gemmBlocks, 128, SMEM128>>>(x, W1, A, n);
    agg128_kernel<<<nodeWarpBlocks, 256>>>(rowptr, esrc, ews, A, b1, B, n);
    // ---- layer 2 ----
    gemm128_kernel<<<gemmBlocks, 128, SMEM128>>>(B, W2, A, n);
    agg128_kernel<<<nodeWarpBlocks, 256>>>(rowptr, esrc, ews, A, b2, B, n);
    // ---- layer 3 (D_OUT = 40) ----
    gemm40_kernel<<<gemm40Blocks, 320, SMEM40>>>(B, W3, A, n);
    agg40_lsm_kernel<<<nodeWarpBlocks, 256>>>(rowptr, esrc, ews, A, b3, out, n);
}

// round 5
// speedup vs baseline: 3.4460x; 1.3076x over previous
#include <cuda_runtime.h>
#include <cstdint>

// ---------------------------------------------------------------------------
// AdjGCN: 3-layer GCN forward, CSR-gather aggregation (no float atomics).
// CSR build runs on a forked side stream, overlapped with layer-1 GEMM.
// ---------------------------------------------------------------------------

#define MAXN 100000
#define MAXE 1600000
#define DH   128
#define DO   40

__device__ float g_bufA[(size_t)MAXN * DH];
__device__ float g_bufB[(size_t)MAXN * DH];
__device__ int   g_idx64;            // 1 if edge_index is int64, 0 if int32
__device__ int   g_rowptr[MAXN + 1];
__device__ int   g_deg[MAXN];
__device__ int   g_fill[MAXN];
__device__ int   g_esrc[MAXE];
__device__ float g_ews[MAXE];
__device__ int   g_partials[128];

// ---------------------------------------------------------------------------
__device__ __forceinline__ void load_edge(const void* ei, int nedges, int e,
                                          int& s, int& d) {
    if (g_idx64) {
        const long long* p = (const long long*)ei;
        s = (int)p[e];
        d = (int)p[(size_t)nedges + e];
    } else {
        const int* p = (const int*)ei;
        s = p[e];
        d = p[(size_t)nedges + e];
    }
}

// ------------------------------ CSR build ---------------------------------
__global__ void deg_zero_kernel(int* __restrict__ deg, int n,
                                const void* ei, int n_nodes) {
    int i = blockIdx.x * blockDim.x + threadIdx.x;
    if (i < n) deg[i] = 0;
    if (blockIdx.x == 0 && threadIdx.x == 0) {
        const long long* p = (const long long*)ei;
        int ok64 = 1;
        for (int k = 0; k < 32; k++) {
            long long v = p[k];
            if (v < 0 || v >= n_nodes) { ok64 = 0; break; }
        }
        g_idx64 = ok64;
    }
}

__global__ void deg_count_kernel(const void* __restrict__ ei, int ne,
                                 int* __restrict__ deg) {
    int e = blockIdx.x * blockDim.x + threadIdx.x;
    if (e < ne) {
        int s, d;
        load_edge(ei, ne, e, s, d);
        atomicAdd(&deg[d], 1);
    }
}

__global__ void scan_block_kernel(const int* __restrict__ deg,
                                  int* __restrict__ rowptr,
                                  int* __restrict__ partials, int n) {
    __shared__ int sm[1024];
    const int tid = threadIdx.x;
    int i = blockIdx.x * 1024 + tid;
    int v = (i < n) ? deg[i] : 0;
    sm[tid] = v;
    __syncthreads();
#pragma unroll
    for (int o = 1; o < 1024; o <<= 1) {
        int t = (tid >= o) ? sm[tid - o] : 0;
        __syncthreads();
        sm[tid] += t;
        __syncthreads();
    }
    if (i < n) rowptr[i] = sm[tid] - v;
    if (tid == 1023) partials[blockIdx.x] = sm[1023];
}

__global__ void scan_partials_kernel(int* __restrict__ partials, int nb) {
    __shared__ int sm[128];
    const int tid = threadIdx.x;
    int v = (tid < nb) ? partials[tid] : 0;
    sm[tid] = v;
    __syncthreads();
#pragma unroll
    for (int o = 1; o < 128; o <<= 1) {
        int t = (tid >= o) ? sm[tid - o] : 0;
        __syncthreads();
        sm[tid] += t;
        __syncthreads();
    }
    if (tid < nb) partials[tid] = sm[tid] - v;
}

__global__ void scan_add_kernel(int* __restrict__ rowptr,
                                const int* __restrict__ partials,
                                int* __restrict__ fill, int n, int ne) {
    int i = blockIdx.x * blockDim.x + threadIdx.x;
    if (i < n) {
        int v = rowptr[i] + partials[i >> 10];
        rowptr[i] = v;
        fill[i] = v;
    }
    if (i == 0) rowptr[n] = ne;
}

__global__ void csr_fill_kernel(const void* __restrict__ ei,
                                const float* __restrict__ ew, int ne,
                                int* __restrict__ fill,
                                int* __restrict__ esrc,
                                float* __restrict__ ews) {
    int e = blockIdx.x * blockDim.x + threadIdx.x;
    if (e < ne) {
        int s, d;
        load_edge(ei, ne, e, s, d);
        int pos = atomicAdd(&fill[d], 1);
        esrc[pos] = s;
        ews[pos] = ew[e];
    }
}

// ------------------------------ GEMMs -------------------------------------
// 128x128 W resident in smem; 64 rows/block, 256 threads; 8 rows x 4 cols
// register tile per thread; float4-over-k loads.
__global__ void gemm128_kernel(const float* __restrict__ X,
                               const float* __restrict__ W,
                               float* __restrict__ Y, int nrows) {
    extern __shared__ float sm[];
    float* Ws = sm;                 // 128*128  (64 KB)
    float* Xs = sm + 128 * 128;     // 64*128   (32 KB)
    const int tid = threadIdx.x;

    const float4* W4 = (const float4*)W;
    float4* Ws4 = (float4*)Ws;
#pragma unroll
    for (int i = tid; i < 128 * 32; i += 256) Ws4[i] = W4[i];

    const int row0 = blockIdx.x * 64;
    const float4* X4 = (const float4*)X;
    float4* Xs4 = (float4*)Xs;
#pragma unroll
    for (int i = tid; i < 64 * 32; i += 256) {
        int gr = row0 + (i >> 5);
        Xs4[i] = (gr < nrows) ? X4[(size_t)gr * 32 + (i & 31)]
                              : make_float4(0.f, 0.f, 0.f, 0.f);
    }
    __syncthreads();

    const int cg = tid & 31;    // cols 4*cg..4*cg+3
    const int rg = tid >> 5;    // rows 8*rg..8*rg+7 (0..7)

    float acc[8][4];
#pragma unroll
    for (int r = 0; r < 8; r++) {
        acc[r][0] = 0.f; acc[r][1] = 0.f; acc[r][2] = 0.f; acc[r][3] = 0.f;
    }
    const float4* xb4 = (const float4*)(Xs + rg * 8 * 128);
    const float4* Wsv = (const float4*)Ws;

#pragma unroll 4
    for (int k4 = 0; k4 < 32; k4++) {
        float4 xv[8];
#pragma unroll
        for (int r = 0; r < 8; r++) xv[r] = xb4[r * 32 + k4];
        float4 w0 = Wsv[(4 * k4 + 0) * 32 + cg];
        float4 w1 = Wsv[(4 * k4 + 1) * 32 + cg];
        float4 w2 = Wsv[(4 * k4 + 2) * 32 + cg];
        float4 w3 = Wsv[(4 * k4 + 3) * 32 + cg];
#pragma unroll
        for (int r = 0; r < 8; r++) {
            acc[r][0] += xv[r].x * w0.x + xv[r].y * w1.x
                       + xv[r].z * w2.x + xv[r].w * w3.x;
            acc[r][1] += xv[r].x * w0.y + xv[r].y * w1.y
                       + xv[r].z * w2.y + xv[r].w * w3.y;
            acc[r][2] += xv[r].x * w0.z + xv[r].y * w1.z
                       + xv[r].z * w2.z + xv[r].w * w3.z;
            acc[r][3] += xv[r].x * w0.w + xv[r].y * w1.w
                       + xv[r].z * w2.w + xv[r].w * w3.w;
        }
    }

#pragma unroll
    for (int r = 0; r < 8; r++) {
        int gr = row0 + rg * 8 + r;
        if (gr < nrows) {
            ((float4*)Y)[(size_t)gr * 32 + cg] =
                make_float4(acc[r][0], acc[r][1], acc[r][2], acc[r][3]);
        }
    }
}

// D_OUT=40: 320 threads (8 row-groups x 40 cols), 64 rows/block.
__global__ void gemm40_kernel(const float* __restrict__ X,
                              const float* __restrict__ W,
                              float* __restrict__ Y, int nrows) {
    extern __shared__ float sm[];
    float* Ws = sm;                 // 128*40
    float* Xs = sm + 128 * DO;      // 64*128
    const int tid = threadIdx.x;

    for (int i = tid; i < 128 * DO; i += 320) Ws[i] = W[i];

    const int row0 = blockIdx.x * 64;
    const float4* X4 = (const float4*)X;
    float4* Xs4 = (float4*)Xs;
    for (int i = tid; i < 64 * 32; i += 320) {
        int gr = row0 + (i >> 5);
        Xs4[i] = (gr < nrows) ? X4[(size_t)gr * 32 + (i & 31)]
                              : make_float4(0.f, 0.f, 0.f, 0.f);
    }
    __syncthreads();

    const int c  = tid % DO;
    const int rg = tid / DO;    // 0..7
    float acc[8];
#pragma unroll
    for (int r = 0; r < 8; r++) acc[r] = 0.f;
    const float4* xb4 = (const float4*)(Xs + rg * 8 * 128);

#pragma unroll 4
    for (int k4 = 0; k4 < 32; k4++) {
        float w0 = Ws[(4 * k4 + 0) * DO + c];
        float w1 = Ws[(4 * k4 + 1) * DO + c];
        float w2 = Ws[(4 * k4 + 2) * DO + c];
        float w3 = Ws[(4 * k4 + 3) * DO + c];
#pragma unroll
        for (int r = 0; r < 8; r++) {
            float4 xv = xb4[r * 32 + k4];
            acc[r] += xv.x * w0 + xv.y * w1 + xv.z * w2 + xv.w * w3;
        }
    }
#pragma unroll
    for (int r = 0; r < 8; r++) {
        int gr = row0 + rg * 8 + r;
        if (gr < nrows) Y[(size_t)gr * DO + c] = acc[r];
    }
}

// ----------------------- CSR gather aggregation ----------------------------
__global__ void agg128_kernel(const int* __restrict__ rowptr,
                              const int* __restrict__ esrc,
                              const float* __restrict__ ews,
                              const float* __restrict__ H,
                              const float* __restrict__ bias,
                              float* __restrict__ Y, int n) {
    int node = blockIdx.x * 8 + (threadIdx.x >> 5);
    if (node >= n) return;
    const int lane = threadIdx.x & 31;
    int beg = rowptr[node];
    int end = rowptr[node + 1];

    float4 acc = make_float4(0.f, 0.f, 0.f, 0.f);
    int j = beg;
    for (; j + 3 < end; j += 4) {
        int s0 = esrc[j];     float w0 = ews[j];
        int s1 = esrc[j + 1]; float w1 = ews[j + 1];
        int s2 = esrc[j + 2]; float w2 = ews[j + 2];
        int s3 = esrc[j + 3]; float w3 = ews[j + 3];
        float4 v0 = ((const float4*)(H + (size_t)s0 * 128))[lane];
        float4 v1 = ((const float4*)(H + (size_t)s1 * 128))[lane];
        float4 v2 = ((const float4*)(H + (size_t)s2 * 128))[lane];
        float4 v3 = ((const float4*)(H + (size_t)s3 * 128))[lane];
        acc.x += v0.x * w0 + v1.x * w1 + v2.x * w2 + v3.x * w3;
        acc.y += v0.y * w0 + v1.y * w1 + v2.y * w2 + v3.y * w3;
        acc.z += v0.z * w0 + v1.z * w1 + v2.z * w2 + v3.z * w3;
        acc.w += v0.w * w0 + v1.w * w1 + v2.w * w2 + v3.w * w3;
    }
    for (; j < end; j++) {
        int s = esrc[j]; float w = ews[j];
        float4 v = ((const float4*)(H + (size_t)s * 128))[lane];
        acc.x += v.x * w; acc.y += v.y * w; acc.z += v.z * w; acc.w += v.w * w;
    }

    float4 b = ((const float4*)bias)[lane];
    acc.x = fmaxf(acc.x + b.x, 0.f);
    acc.y = fmaxf(acc.y + b.y, 0.f);
    acc.z = fmaxf(acc.z + b.z, 0.f);
    acc.w = fmaxf(acc.w + b.w, 0.f);
    ((float4*)(Y + (size_t)node * 128))[lane] = acc;
}

// D=40 gather + bias + log_softmax, one warp per node.
__global__ void agg40_lsm_kernel(const int* __restrict__ rowptr,
                                 const int* __restrict__ esrc,
                                 const float* __restrict__ ews,
                                 const float* __restrict__ H,
                                 const float* __restrict__ b,
                                 float* __restrict__ out, int n) {
    int node = blockIdx.x * 8 + (threadIdx.x >> 5);
    if (node >= n) return;
    const int lane = threadIdx.x & 31;
    int beg = rowptr[node];
    int end = rowptr[node + 1];

    float a0 = 0.f, a1 = 0.f;
    int j = beg;
    for (; j + 1 < end; j += 2) {
        int s0 = esrc[j];     float w0 = ews[j];
        int s1 = esrc[j + 1]; float w1 = ews[j + 1];
        const float* h0 = H + (size_t)s0 * DO;
        const float* h1 = H + (size_t)s1 * DO;
        a0 += h0[lane] * w0 + h1[lane] * w1;
        if (lane < 8) a1 += h0[32 + lane] * w0 + h1[32 + lane] * w1;
    }
    if (j < end) {
        int s = esrc[j]; float w = ews[j];
        const float* hs = H + (size_t)s * DO;
        a0 += hs[lane] * w;
        if (lane < 8) a1 += hs[32 + lane] * w;
    }

    float v0 = a0 + b[lane];
    float v1 = (lane < 8) ? (a1 + b[32 + lane]) : -1e30f;

    float m = fmaxf(v0, v1);
#pragma unroll
    for (int o = 16; o; o >>= 1) m = fmaxf(m, __shfl_xor_sync(0xffffffffu, m, o));

    float sum = __expf(v0 - m) + ((lane < 8) ? __expf(v1 - m) : 0.f);
#pragma unroll
    for (int o = 16; o; o >>= 1) sum += __shfl_xor_sync(0xffffffffu, sum, o);

    float lse = m + __logf(sum);
    out[(size_t)node * DO + lane] = v0 - lse;
    if (lane < 8) out[(size_t)node * DO + 32 + lane] = v1 - lse;
}

// ---------------------------------------------------------------------------
extern "C" void kernel_launch(void* const* d_in, const int* in_sizes, int n_in,
                              void* d_out, int out_size) {
    const float* x  = (const float*)d_in[0];
    const void*  ei = d_in[1];
    const float* ew = (const float*)d_in[2];
    const float* W1 = (const float*)d_in[3];
    const float* b1 = (const float*)d_in[4];
    const float* W2 = (const float*)d_in[5];
    const float* b2 = (const float*)d_in[6];
    const float* W3 = (const float*)d_in[7];
    const float* b3 = (const float*)d_in[8];
    float* out = (float*)d_out;

    const int n  = in_sizes[0] / DH;
    int ne = in_sizes[1] / 2;
    if (ne > MAXE) ne = MAXE;
    (void)n_in; (void)out_size;

    float *A, *B;
    int *rowptr, *deg, *fill, *esrc, *partials;
    float* ews;
    cudaGetSymbolAddress((void**)&A, g_bufA);
    cudaGetSymbolAddress((void**)&B, g_bufB);
    cudaGetSymbolAddress((void**)&rowptr, g_rowptr);
    cudaGetSymbolAddress((void**)&deg, g_deg);
    cudaGetSymbolAddress((void**)&fill, g_fill);
    cudaGetSymbolAddress((void**)&esrc, g_esrc);
    cudaGetSymbolAddress((void**)&ews, g_ews);
    cudaGetSymbolAddress((void**)&partials, g_partials);

    const int SMEM128 = (128 * 128 + 64 * 128) * (int)sizeof(float); // 96 KB
    const int SMEM40  = (128 * DO + 64 * 128) * (int)sizeof(float);  // 52.5 KB
    cudaFuncSetAttribute(gemm128_kernel,
                         cudaFuncAttributeMaxDynamicSharedMemorySize, SMEM128);
    cudaFuncSetAttribute(gemm40_kernel,
                         cudaFuncAttributeMaxDynamicSharedMemorySize, SMEM40);

    const int gemmBlocks     = (n + 63) / 64;
    const int nodeWarpBlocks = (n + 7) / 8;
    const int scanBlocks     = (n + 1023) / 1024;

    // Lazily created side stream + events for the CSR/GEMM overlap.
    static cudaStream_t s2 = nullptr;
    static cudaEvent_t evFork = nullptr, evJoin = nullptr;
    if (s2 == nullptr) {
        cudaStreamCreateWithFlags(&s2, cudaStreamNonBlocking);
        cudaEventCreateWithFlags(&evFork, cudaEventDisableTiming);
        cudaEventCreateWithFlags(&evJoin, cudaEventDisableTiming);
    }

    // ---- fork: CSR build (by dst) on side stream ----
    cudaEventRecord(evFork, 0);
    cudaStreamWaitEvent(s2, evFork, 0);
    deg_zero_kernel<<<(n + 255) / 256, 256, 0, s2>>>(deg, n, ei, n);
    deg_count_kernel<<<(ne + 255) / 256, 256, 0, s2>>>(ei, ne, deg);
    scan_block_kernel<<<scanBlocks, 1024, 0, s2>>>(deg, rowptr, partials, n);
    scan_partials_kernel<<<1, 128, 0, s2>>>(partials, scanBlocks);
    scan_add_kernel<<<(n + 255) / 256, 256, 0, s2>>>(rowptr, partials, fill, n, ne);
    csr_fill_kernel<<<(ne + 255) / 256, 256, 0, s2>>>(ei, ew, ne, fill, esrc, ews);
    cudaEventRecord(evJoin, s2);

    // ---- main stream: layer-1 GEMM overlaps CSR build ----
    gemm128_kernel<<<gemmBlocks, 256, SMEM128>>>(x, W1, A, n);

    // ---- join ----
    cudaStreamWaitEvent(0, evJoin, 0);

    // ---- layer 1 aggregation ----
    agg128_kernel<<<nodeWarpBlocks, 256>>>(rowptr, esrc, ews, A, b1, B, n);
    // ---- layer 2 ----
    gemm128_kernel<<<gemmBlocks, 256, SMEM128>>>(B, W2, A, n);
    agg128_kernel<<<nodeWarpBlocks, 256>>>(rowptr, esrc, ews, A, b2, B, n);
    // ---- layer 3 (D_OUT = 40) ----
    gemm40_kernel<<<gemmBlocks, 320, SMEM40>>>(B, W3, A, n);
    agg40_lsm_kernel<<<nodeWarpBlocks, 256>>>(rowptr, esrc, ews, A, b3, out, n);
}